// round 11
// baseline (speedup 1.0000x reference)
#include <cuda_runtime.h>
#include <cuda_bf16.h>
#include <cstdint>

#define HDIM 256
#define NMAX 50048

// ---------------- static scratch ----------------
__device__ float g_buf0[NMAX * HDIM];    // gemm4 out (pre-LN)
__device__ float g_buf1[NMAX * HDIM];    // gemm2 out (msg, fp32 for scatter)
__device__ float g_accum[NMAX * HDIM];   // scatter-sum
__device__ float g_counts[NMAX];
__device__ int   g_idx64;

// pre-split bf16 activations (hi/lo)
__device__ __nv_bfloat16 g_a0h[NMAX * 256], g_a0l[NMAX * 256];   // split(source)
__device__ __nv_bfloat16 g_a1h[NMAX * 256], g_a1l[NMAX * 256];   // gemm1 out
__device__ __nv_bfloat16 g_a3h[NMAX * 512], g_a3l[NMAX * 512];   // [target | accum/cnt]
__device__ __nv_bfloat16 g_a4h[NMAX * 256], g_a4l[NMAX * 256];   // gemm3 out

// split weights, transposed to [N, K] (K contiguous)
__device__ __nv_bfloat16 g_w0h[256 * 256], g_w0l[256 * 256];
__device__ __nv_bfloat16 g_w1h[256 * 256], g_w1l[256 * 256];
__device__ __nv_bfloat16 g_w2h[256 * 512], g_w2l[256 * 512];
__device__ __nv_bfloat16 g_w3h[256 * 256], g_w3l[256 * 256];

__device__ __forceinline__ float gelu_exact(float x) { return x * normcdff(x); }

__device__ __forceinline__ uint32_t smem_u32(const void* p) {
    uint32_t a;
    asm("{ .reg .u64 t; cvta.to.shared.u64 t, %1; cvt.u32.u64 %0, t; }" : "=r"(a) : "l"(p));
    return a;
}

#define LDMX4(r0, r1, r2, r3, a) \
    asm volatile("ldmatrix.sync.aligned.m8n8.x4.shared.b16 {%0,%1,%2,%3}, [%4];" \
        : "=r"(r0), "=r"(r1), "=r"(r2), "=r"(r3) : "r"(a))

#define MMA16816(c, a0, a1, a2, a3, b0, b1) \
    asm volatile("mma.sync.aligned.m16n8k16.row.col.f32.bf16.bf16.f32 " \
        "{%0,%1,%2,%3}, {%4,%5,%6,%7}, {%8,%9}, {%0,%1,%2,%3};" \
        : "+f"((c)[0]), "+f"((c)[1]), "+f"((c)[2]), "+f"((c)[3]) \
        : "r"(a0), "r"(a1), "r"(a2), "r"(a3), "r"(b0), "r"(b1))

#define CPASYNC16(sm, gp) \
    asm volatile("cp.async.cg.shared.global [%0], [%1], 16;" :: "r"(sm), "l"(gp))
#define CPASYNC_COMMIT() asm volatile("cp.async.commit_group;" ::: "memory")
#define CPASYNC_WAIT1()  asm volatile("cp.async.wait_group 1;" ::: "memory")

__device__ __forceinline__ uint32_t pack_bf2(__nv_bfloat16 a, __nv_bfloat16 b) {
    __nv_bfloat162 t = __halves2bfloat162(a, b);
    return *(uint32_t*)&t;
}
__device__ __forceinline__ void split2(float v0, float v1, uint32_t& hp, uint32_t& lp) {
    __nv_bfloat16 h0 = __float2bfloat16_rn(v0);
    __nv_bfloat16 h1 = __float2bfloat16_rn(v1);
    __nv_bfloat16 l0 = __float2bfloat16_rn(v0 - __bfloat162float(h0));
    __nv_bfloat16 l1 = __float2bfloat16_rn(v1 - __bfloat162float(h1));
    hp = pack_bf2(h0, h1);
    lp = pack_bf2(l0, l1);
}

// ---------------- small kernels ----------------
__global__ void detect_idx_kernel(const void* eidx, int nnodes) {
    const long long* p = (const long long*)eidx;
    int ok64 = 1;
    #pragma unroll 1
    for (int i = 0; i < 64; i++) {
        long long v = p[i];
        if (v < 0 || v >= (long long)nnodes) { ok64 = 0; break; }
    }
    g_idx64 = ok64;
}

// All four W[K,N] fp32 -> Wt_hi/Wt_lo[N,K] bf16 splits in one launch.
__global__ void wprep_all_kernel(const float* __restrict__ W0,
                                 const float* __restrict__ W1,
                                 const float* __restrict__ W2,
                                 const float* __restrict__ W3) {
    int idx = blockIdx.x * blockDim.x + threadIdx.x;
    const float* W; __nv_bfloat16 *Wh, *Wl; int K;
    if (idx < 65536)       { W = W0; Wh = g_w0h; Wl = g_w0l; K = 256; }
    else if (idx < 131072) { W = W1; Wh = g_w1h; Wl = g_w1l; K = 256; idx -= 65536; }
    else if (idx < 262144) { W = W2; Wh = g_w2h; Wl = g_w2l; K = 512; idx -= 131072; }
    else if (idx < 327680) { W = W3; Wh = g_w3h; Wl = g_w3l; K = 256; idx -= 262144; }
    else return;
    const int n = idx / K, k = idx - n * K;
    const float w = W[(size_t)k * 256 + n];
    const __nv_bfloat16 h = __float2bfloat16_rn(w);
    Wh[idx] = h;
    Wl[idx] = __float2bfloat16_rn(w - __bfloat162float(h));
}

// source fp32 [M,256] -> hi/lo bf16 (8 elems per thread)
__global__ void split_src_kernel(const float* __restrict__ src,
                                 __nv_bfloat16* __restrict__ H,
                                 __nv_bfloat16* __restrict__ L, int n8) {
    const int i = blockIdx.x * blockDim.x + threadIdx.x;
    if (i >= n8) return;
    const float4 v0 = ((const float4*)src)[i * 2];
    const float4 v1 = ((const float4*)src)[i * 2 + 1];
    uint32_t h[4], l[4];
    split2(v0.x, v0.y, h[0], l[0]);
    split2(v0.z, v0.w, h[1], l[1]);
    split2(v1.x, v1.y, h[2], l[2]);
    split2(v1.z, v1.w, h[3], l[3]);
    ((uint4*)H)[i] = *(uint4*)h;
    ((uint4*)L)[i] = *(uint4*)l;
}

// build [M,512] hi/lo: cols 0-255 = target, 256-511 = accum/max(count,1)
__global__ void split_comb_kernel(const float* __restrict__ target,
                                  const float* __restrict__ accum,
                                  const float* __restrict__ counts, int M) {
    const int i = blockIdx.x * blockDim.x + threadIdx.x;
    if (i >= M * 64) return;          // 64 groups of 8 per row
    const int row = i >> 6;
    const int c0 = (i & 63) * 8;
    float f[8];
    if (c0 < 256) {
        const float4 v0 = *(const float4*)(target + (size_t)row * 256 + c0);
        const float4 v1 = *(const float4*)(target + (size_t)row * 256 + c0 + 4);
        f[0] = v0.x; f[1] = v0.y; f[2] = v0.z; f[3] = v0.w;
        f[4] = v1.x; f[5] = v1.y; f[6] = v1.z; f[7] = v1.w;
    } else {
        const float inv = 1.0f / fmaxf(counts[row], 1.0f);
        const float4 v0 = *(const float4*)(accum + (size_t)row * 256 + (c0 - 256));
        const float4 v1 = *(const float4*)(accum + (size_t)row * 256 + (c0 - 256) + 4);
        f[0] = v0.x * inv; f[1] = v0.y * inv; f[2] = v0.z * inv; f[3] = v0.w * inv;
        f[4] = v1.x * inv; f[5] = v1.y * inv; f[6] = v1.z * inv; f[7] = v1.w * inv;
    }
    uint32_t h[4], l[4];
    #pragma unroll
    for (int j = 0; j < 4; j++) split2(f[2 * j], f[2 * j + 1], h[j], l[j]);
    ((uint4*)g_a3h)[i] = *(uint4*)h;
    ((uint4*)g_a3l)[i] = *(uint4*)l;
}

// ---------------- mma.sync GEMM: all-cp.async mainloop ----------------
// C = act(A @ Wt^T + b). A pre-split bf16 hi/lo [M,Kw]; Wt [N,Kw] hi/lo.
// 3xBF16 accumulation. CTA 64x128, BK=32, 256 thr = 8 warps (2m x 4n),
// warp tile 32x32, 2 CTAs/SM. 3-stage fused A+B ring, depth-1 prefetch,
// one __syncthreads per chunk (write (ch+1)%3 is distance >=2 from any
// laggard's read stage).
// Stage layout (stride 30720): Ah[0,5120) Al[5120,10240)
//                              Bh[10240,20480) Bl[20480,30720)
#define STG_STRIDE 30720
#define SM_TOTAL (3 * STG_STRIDE)

template<int KCHUNKS, int OUTF32, int OUTSPLIT, int RESID>
__global__ __launch_bounds__(256, 2)
void gemm_bf16(const __nv_bfloat16* __restrict__ Ah, const __nv_bfloat16* __restrict__ Al,
               const __nv_bfloat16* __restrict__ Wh, const __nv_bfloat16* __restrict__ Wl,
               int Kw, const float* __restrict__ bias, const float* __restrict__ resid,
               float* __restrict__ Cf,
               __nv_bfloat16* __restrict__ Ch, __nv_bfloat16* __restrict__ Cl, int M)
{
    extern __shared__ char smem[];
    const uint32_t sb = smem_u32(smem);
    const int tid = threadIdx.x;
    const int wid = tid >> 5, lane = tid & 31;
    const int rowBlock = blockIdx.y * 64;
    const int colBlock = blockIdx.x * 128;

    const int warp_m = wid & 1;          // 0..1 -> m offset *32
    const int warp_n = wid >> 1;         // 0..3 -> n offset *32

    float acc[2][4][4];
    #pragma unroll
    for (int a = 0; a < 2; a++)
        #pragma unroll
        for (int b = 0; b < 4; b++)
            #pragma unroll
            for (int c = 0; c < 4; c++) acc[a][b][c] = 0.0f;

    // ldmatrix per-lane addressing (stride 80 bytes per row)
    const int a_rowin = (lane & 7) | (((lane >> 3) & 1) << 3);
    const int a_koff  = ((lane >> 4) & 1) * 8;
    const uint32_t a_byte = (uint32_t)((warp_m * 32 + a_rowin) * 80 + a_koff * 2);
    const int b_rowin = ((lane >> 4) & 1) * 8 + (lane & 7);
    const int b_koff  = ((lane >> 3) & 1) * 8;
    const uint32_t b_byte = (uint32_t)((warp_n * 32 + b_rowin) * 80 + b_koff * 2);

    // cp.async assignments
    const int a_row = tid >> 2, a_p = tid & 3;                 // A: 1x16B per h/l
    auto issueAB = [&](int ch) {
        if (ch < KCHUNKS) {
            const uint32_t base = sb + (uint32_t)(ch % 3) * STG_STRIDE;
            {
                const size_t g = (size_t)(rowBlock + a_row) * Kw + ch * 32 + a_p * 8;
                const uint32_t so = (uint32_t)(a_row * 80 + a_p * 16);
                CPASYNC16(base + so, Ah + g);
                CPASYNC16(base + 5120 + so, Al + g);
            }
            #pragma unroll
            for (int q = 0; q < 2; q++) {                      // B: 2x16B per h/l
                const int s2 = tid * 2 + q;
                const int n = s2 >> 2, p = s2 & 3;
                const size_t g = (size_t)(colBlock + n) * Kw + ch * 32 + p * 8;
                const uint32_t so = (uint32_t)(n * 80 + p * 16);
                CPASYNC16(base + 10240 + so, Wh + g);
                CPASYNC16(base + 20480 + so, Wl + g);
            }
        }
        CPASYNC_COMMIT();
    };

    issueAB(0);

    #pragma unroll 1
    for (int ch = 0; ch < KCHUNKS; ch++) {
        issueAB(ch + 1);
        CPASYNC_WAIT1();
        __syncthreads();

        const uint32_t stg = sb + (uint32_t)(ch % 3) * STG_STRIDE;
        const uint32_t aBase = stg + a_byte;
        const uint32_t bBase = stg + 10240 + b_byte;
        #pragma unroll
        for (int s = 0; s < 2; s++) {
            uint32_t ah[4], al[4], bh[2][4], bl[2][4];
            LDMX4(ah[0], ah[1], ah[2], ah[3], aBase + s * 32);
            LDMX4(al[0], al[1], al[2], al[3], aBase + 5120 + s * 32);
            #pragma unroll
            for (int np = 0; np < 2; np++) {
                LDMX4(bh[np][0], bh[np][1], bh[np][2], bh[np][3], bBase + np * 16 * 80 + s * 32);
                LDMX4(bl[np][0], bl[np][1], bl[np][2], bl[np][3], bBase + 10240 + np * 16 * 80 + s * 32);
            }
            uint32_t ah2[4], al2[4];
            LDMX4(ah2[0], ah2[1], ah2[2], ah2[3], aBase + 16 * 80 + s * 32);
            LDMX4(al2[0], al2[1], al2[2], al2[3], aBase + 5120 + 16 * 80 + s * 32);
            #pragma unroll
            for (int nt = 0; nt < 4; nt++) {
                const int np = nt >> 1, ix = (nt & 1) * 2;
                MMA16816(acc[0][nt], ah[0], ah[1], ah[2], ah[3], bh[np][ix], bh[np][ix + 1]);
                MMA16816(acc[0][nt], ah[0], ah[1], ah[2], ah[3], bl[np][ix], bl[np][ix + 1]);
                MMA16816(acc[0][nt], al[0], al[1], al[2], al[3], bh[np][ix], bh[np][ix + 1]);
                MMA16816(acc[1][nt], ah2[0], ah2[1], ah2[2], ah2[3], bh[np][ix], bh[np][ix + 1]);
                MMA16816(acc[1][nt], ah2[0], ah2[1], ah2[2], ah2[3], bl[np][ix], bl[np][ix + 1]);
                MMA16816(acc[1][nt], al2[0], al2[1], al2[2], al2[3], bh[np][ix], bh[np][ix + 1]);
            }
        }
    }

    // ---- epilogue ----
    const int qr = lane >> 2;
    const int qc = (lane & 3) * 2;
    float bv[4][2];
    #pragma unroll
    for (int nt = 0; nt < 4; nt++) {
        const int col = colBlock + warp_n * 32 + nt * 8 + qc;
        bv[nt][0] = bias[col];
        bv[nt][1] = bias[col + 1];
    }
    #pragma unroll
    for (int mt = 0; mt < 2; mt++)
        #pragma unroll
        for (int half = 0; half < 2; half++) {
            const int row = rowBlock + warp_m * 32 + mt * 16 + qr + half * 8;
            if (row >= M) continue;
            #pragma unroll
            for (int nt = 0; nt < 4; nt++) {
                const int col = colBlock + warp_n * 32 + nt * 8 + qc;
                float v0 = gelu_exact(acc[mt][nt][half * 2 + 0] + bv[nt][0]);
                float v1 = gelu_exact(acc[mt][nt][half * 2 + 1] + bv[nt][1]);
                if (RESID) {
                    const float2 rv = *(const float2*)(resid + (size_t)row * 256 + col);
                    v0 += rv.x; v1 += rv.y;
                }
                if (OUTF32)
                    *(float2*)(Cf + (size_t)row * 256 + col) = make_float2(v0, v1);
                if (OUTSPLIT) {
                    uint32_t hp, lp;
                    split2(v0, v1, hp, lp);
                    *(uint32_t*)(Ch + (size_t)row * 256 + col) = hp;
                    *(uint32_t*)(Cl + (size_t)row * 256 + col) = lp;
                }
            }
        }
}

// ---------------- edge scatter-sum (2 edges per warp iteration) ----------------
__global__ void scatter_kernel(const void* __restrict__ eidx,
                               const float* __restrict__ msg,
                               float* __restrict__ accum,
                               float* __restrict__ counts,
                               int E, int Nn)
{
    const int lane = threadIdx.x & 31;
    const int warp = (blockIdx.x * blockDim.x + threadIdx.x) >> 5;
    const int nwarps = (gridDim.x * blockDim.x) >> 5;
    const int flag = g_idx64;
    const long long* p64 = (const long long*)eidx;
    const int*       p32 = (const int*)eidx;

    #pragma unroll 1
    for (int e = warp * 2; e < E; e += nwarps * 2) {
        const int e1ok = (e + 1 < E);
        int src0, dst0, src1 = 0, dst1 = 0;
        if (flag) {
            src0 = (int)p64[e]; dst0 = (int)p64[E + e];
            if (e1ok) { src1 = (int)p64[e + 1]; dst1 = (int)p64[E + e + 1]; }
        } else {
            src0 = p32[e]; dst0 = p32[E + e];
            if (e1ok) { src1 = p32[e + 1]; dst1 = p32[E + e + 1]; }
        }
        src0 = min(max(src0, 0), Nn - 1); dst0 = min(max(dst0, 0), Nn - 1);
        src1 = min(max(src1, 0), Nn - 1); dst1 = min(max(dst1, 0), Nn - 1);

        const float4* s0 = (const float4*)(msg + (size_t)src0 * 256);
        const float4* s1 = (const float4*)(msg + (size_t)src1 * 256);
        const float4 a0 = s0[lane * 2 + 0];
        const float4 a1 = s0[lane * 2 + 1];
        float4 b0 = make_float4(0.f, 0.f, 0.f, 0.f);
        float4 b1 = make_float4(0.f, 0.f, 0.f, 0.f);
        if (e1ok) { b0 = s1[lane * 2 + 0]; b1 = s1[lane * 2 + 1]; }

        float* d0 = accum + (size_t)dst0 * 256 + lane * 8;
        asm volatile("red.global.add.v4.f32 [%0], {%1,%2,%3,%4};"
                     :: "l"(d0), "f"(a0.x), "f"(a0.y), "f"(a0.z), "f"(a0.w) : "memory");
        asm volatile("red.global.add.v4.f32 [%0], {%1,%2,%3,%4};"
                     :: "l"(d0 + 4), "f"(a1.x), "f"(a1.y), "f"(a1.z), "f"(a1.w) : "memory");
        if (e1ok) {
            float* d1 = accum + (size_t)dst1 * 256 + lane * 8;
            asm volatile("red.global.add.v4.f32 [%0], {%1,%2,%3,%4};"
                         :: "l"(d1), "f"(b0.x), "f"(b0.y), "f"(b0.z), "f"(b0.w) : "memory");
            asm volatile("red.global.add.v4.f32 [%0], {%1,%2,%3,%4};"
                         :: "l"(d1 + 4), "f"(b1.x), "f"(b1.y), "f"(b1.z), "f"(b1.w) : "memory");
        }
        if (lane == 0) {
            asm volatile("red.global.add.f32 [%0], %1;"
                         :: "l"(counts + dst0), "f"(1.0f) : "memory");
            if (e1ok)
                asm volatile("red.global.add.f32 [%0], %1;"
                             :: "l"(counts + dst1), "f"(1.0f) : "memory");
        }
    }
}

// ---------------- LayerNorm (warp per row) ----------------
__global__ __launch_bounds__(256)
void ln_kernel(const float* __restrict__ X, const float* __restrict__ gamma,
               const float* __restrict__ beta, float* __restrict__ out, int M)
{
    const int warp = (blockIdx.x * blockDim.x + threadIdx.x) >> 5;
    const int lane = threadIdx.x & 31;
    if (warp >= M) return;
    const float* xp = X + (size_t)warp * 256 + lane * 8;
    float v[8];
    *(float4*)&v[0] = *(const float4*)(xp);
    *(float4*)&v[4] = *(const float4*)(xp + 4);
    float s = 0.f, sq = 0.f;
    #pragma unroll
    for (int j = 0; j < 8; j++) { s += v[j]; sq += v[j] * v[j]; }
    #pragma unroll
    for (int off = 16; off > 0; off >>= 1) {
        s  += __shfl_xor_sync(0xFFFFFFFFu, s,  off);
        sq += __shfl_xor_sync(0xFFFFFFFFu, sq, off);
    }
    const float mu  = s * (1.0f / 256.0f);
    const float var = sq * (1.0f / 256.0f) - mu * mu;
    const float inv = rsqrtf(var + 1e-5f);
    float o[8];
    #pragma unroll
    for (int j = 0; j < 8; j++)
        o[j] = (v[j] - mu) * inv * gamma[lane * 8 + j] + beta[lane * 8 + j];
    float* dp = out + (size_t)warp * 256 + lane * 8;
    *(float4*)(dp)     = *(float4*)&o[0];
    *(float4*)(dp + 4) = *(float4*)&o[4];
}

// ---------------- launch ----------------
extern "C" void kernel_launch(void* const* d_in, const int* in_sizes, int n_in,
                              void* d_out, int out_size)
{
    const float* source = (const float*)d_in[0];
    const float* target = (const float*)d_in[1];
    const void*  eidx   = d_in[2];
    const int base = (n_in > 3 && in_sizes[3] == 1) ? 4 : 3;
    const float* W0 = (const float*)d_in[base + 0];
    const float* b0 = (const float*)d_in[base + 1];
    const float* W1 = (const float*)d_in[base + 2];
    const float* b1 = (const float*)d_in[base + 3];
    const float* W2 = (const float*)d_in[base + 4];
    const float* b2 = (const float*)d_in[base + 5];
    const float* W3 = (const float*)d_in[base + 6];
    const float* b3 = (const float*)d_in[base + 7];
    const float* gm = (const float*)d_in[base + 8];
    const float* bt = (const float*)d_in[base + 9];

    const int M = in_sizes[0] / HDIM;
    const int E = in_sizes[2] / 2;

    float *buf0, *buf1, *accum, *counts;
    cudaGetSymbolAddress((void**)&buf0,   g_buf0);
    cudaGetSymbolAddress((void**)&buf1,   g_buf1);
    cudaGetSymbolAddress((void**)&accum,  g_accum);
    cudaGetSymbolAddress((void**)&counts, g_counts);
    __nv_bfloat16 *a0h, *a0l, *a1h, *a1l, *a3h, *a3l, *a4h, *a4l;
    cudaGetSymbolAddress((void**)&a0h, g_a0h); cudaGetSymbolAddress((void**)&a0l, g_a0l);
    cudaGetSymbolAddress((void**)&a1h, g_a1h); cudaGetSymbolAddress((void**)&a1l, g_a1l);
    cudaGetSymbolAddress((void**)&a3h, g_a3h); cudaGetSymbolAddress((void**)&a3l, g_a3l);
    cudaGetSymbolAddress((void**)&a4h, g_a4h); cudaGetSymbolAddress((void**)&a4l, g_a4l);
    __nv_bfloat16 *w0h, *w0l, *w1h, *w1l, *w2h, *w2l, *w3h, *w3l;
    cudaGetSymbolAddress((void**)&w0h, g_w0h); cudaGetSymbolAddress((void**)&w0l, g_w0l);
    cudaGetSymbolAddress((void**)&w1h, g_w1h); cudaGetSymbolAddress((void**)&w1l, g_w1l);
    cudaGetSymbolAddress((void**)&w2h, g_w2h); cudaGetSymbolAddress((void**)&w2l, g_w2l);
    cudaGetSymbolAddress((void**)&w3h, g_w3h); cudaGetSymbolAddress((void**)&w3l, g_w3l);

    cudaFuncSetAttribute(gemm_bf16<8, 0, 1, 0>,  cudaFuncAttributeMaxDynamicSharedMemorySize, SM_TOTAL);
    cudaFuncSetAttribute(gemm_bf16<8, 1, 0, 0>,  cudaFuncAttributeMaxDynamicSharedMemorySize, SM_TOTAL);
    cudaFuncSetAttribute(gemm_bf16<16, 0, 1, 0>, cudaFuncAttributeMaxDynamicSharedMemorySize, SM_TOTAL);
    cudaFuncSetAttribute(gemm_bf16<8, 1, 0, 1>,  cudaFuncAttributeMaxDynamicSharedMemorySize, SM_TOTAL);

    // Launch order keeps ncu "-s 5 -c 1" on gemm1:
    //  0 memset, 1 memset, 2 wprep, 3 detect, 4 split_src, 5 gemm1 <- captured
    cudaMemsetAsync(accum, 0, sizeof(float) * (size_t)M * HDIM);
    cudaMemsetAsync(counts, 0, sizeof(float) * (size_t)M);
    wprep_all_kernel<<<(327680 + 255) / 256, 256>>>(W0, W1, W2, W3);
    detect_idx_kernel<<<1, 1>>>(eidx, M);
    split_src_kernel<<<(M * 32 + 255) / 256, 256>>>(source, a0h, a0l, M * 32);

    const dim3 gG(2, (M + 63) / 64);
    gemm_bf16<8, 0, 1, 0><<<gG, 256, SM_TOTAL>>>(a0h, a0l, w0h, w0l, 256, b0, nullptr,
                                                 nullptr, a1h, a1l, M);
    gemm_bf16<8, 1, 0, 0><<<gG, 256, SM_TOTAL>>>(a1h, a1l, w1h, w1l, 256, b1, nullptr,
                                                 buf1, nullptr, nullptr, M);

    scatter_kernel<<<2960, 256>>>(eidx, buf1, accum, counts, E, M);

    split_comb_kernel<<<(M * 64 + 255) / 256, 256>>>(target, accum, counts, M);

    gemm_bf16<16, 0, 1, 0><<<gG, 256, SM_TOTAL>>>(a3h, a3l, w2h, w2l, 512, b2, nullptr,
                                                  nullptr, a4h, a4l, M);
    gemm_bf16<8, 1, 0, 1><<<gG, 256, SM_TOTAL>>>(a4h, a4l, w3h, w3l, 256, b3, target,
                                                 buf0, nullptr, nullptr, M);

    ln_kernel<<<(M * 32 + 255) / 256, 256>>>(buf0, gm, bt, (float*)d_out, M);
}